// round 1
// baseline (speedup 1.0000x reference)
#include <cuda_runtime.h>
#include <cstdint>

#define T_TOK 8192
#define D_IN  1024
#define D_OUT 1024
#define NE    8
#define TM    128
#define TN    128
#define BK    16
#define MAXTILES (T_TOK/TM + NE)   // 72

// ---------------- device scratch (no allocations allowed) ----------------
__device__ float g_gate_sum[NE];
__device__ int   g_top1[T_TOK];
__device__ int   g_count[NE];
__device__ int   g_cursor[NE];
__device__ int   g_perm[T_TOK];
__device__ int   g_tile_e[MAXTILES];
__device__ int   g_tile_row[MAXTILES];
__device__ int   g_tile_nrows[MAXTILES];
__device__ int   g_ntiles;

// ---------------- reset ----------------
__global__ void reset_kernel() {
    int i = threadIdx.x;
    if (i < NE) { g_gate_sum[i] = 0.f; g_count[i] = 0; }
}

// ---------------- gate: logits, softmax, top1, per-expert prob sums ------
__global__ void gate_kernel(const float* __restrict__ x,
                            const float* __restrict__ Wg,
                            const float* __restrict__ bg) {
    __shared__ float sWg[NE * D_IN];   // 32 KB
    __shared__ float sSum[NE];
    int tid = threadIdx.x;
    for (int i = tid; i < NE * D_IN; i += blockDim.x) sWg[i] = Wg[i];
    if (tid < NE) sSum[tid] = 0.f;
    __syncthreads();

    int lane = tid & 31, warp = tid >> 5;
    int t = blockIdx.x * (blockDim.x >> 5) + warp;   // one token per warp

    float acc[NE];
#pragma unroll
    for (int e = 0; e < NE; e++) acc[e] = 0.f;
    const float* xp = x + (size_t)t * D_IN;
    for (int d = lane; d < D_IN; d += 32) {
        float xv = xp[d];
#pragma unroll
        for (int e = 0; e < NE; e++) acc[e] = fmaf(xv, sWg[e * D_IN + d], acc[e]);
    }
#pragma unroll
    for (int e = 0; e < NE; e++) {
#pragma unroll
        for (int o = 16; o; o >>= 1) acc[e] += __shfl_xor_sync(0xffffffffu, acc[e], o);
    }

    if (lane == 0) {
        float m = -1e30f; int am = 0;
#pragma unroll
        for (int e = 0; e < NE; e++) {
            acc[e] += bg[e];
            if (acc[e] > m) { m = acc[e]; am = e; }
        }
        float s = 0.f, p[NE];
#pragma unroll
        for (int e = 0; e < NE; e++) { p[e] = expf(acc[e] - m); s += p[e]; }
        float inv = 1.f / s;
        g_top1[t] = am;
        atomicAdd(&g_count[am], 1);
#pragma unroll
        for (int e = 0; e < NE; e++) atomicAdd(&sSum[e], p[e] * inv);
    }
    __syncthreads();
    if (tid < NE) atomicAdd(&g_gate_sum[tid], sSum[tid]);
}

// ---------------- build per-expert tile table (serial, tiny) -------------
__global__ void build_tiles_kernel() {
    if (threadIdx.x == 0) {
        int off = 0, n = 0;
        for (int e = 0; e < NE; e++) {
            g_cursor[e] = off;
            int c = g_count[e];
            int nt = (c + TM - 1) / TM;
            for (int j = 0; j < nt; j++) {
                g_tile_e[n] = e;
                g_tile_row[n] = off + j * TM;
                int rem = c - j * TM;
                g_tile_nrows[n] = rem < TM ? rem : TM;
                n++;
            }
            off += c;
        }
        g_ntiles = n;
    }
}

// ---------------- scatter tokens into per-expert order -------------------
__global__ void scatter_kernel() {
    int t = blockIdx.x * blockDim.x + threadIdx.x;
    if (t < T_TOK) {
        int e = g_top1[t];
        int p = atomicAdd(&g_cursor[e], 1);
        g_perm[p] = t;
    }
}

// ---------------- expert GEMM: 128x128x16 tiles, 8x8/thread, dbl-buf -----
__global__ __launch_bounds__(256, 2)
void gemm_kernel(const float* __restrict__ x, const float* __restrict__ We,
                 const float* __restrict__ be, float* __restrict__ out) {
    int tile = blockIdx.y;
    if (tile >= g_ntiles) return;
    int e     = g_tile_e[tile];
    int row0  = g_tile_row[tile];
    int nrows = g_tile_nrows[tile];
    int o0    = blockIdx.x * TN;

    __shared__ float Xs[2][BK][TM];
    __shared__ float Ws[2][BK][TN];
    __shared__ int   stok[TM];

    int tid = threadIdx.x;
    if (tid < TM) {
        int r = tid < nrows ? tid : nrows - 1;
        stok[tid] = g_perm[row0 + r];
    }
    __syncthreads();

    const float* Wbase = We + (size_t)e * D_OUT * D_IN;
    int lrow  = tid >> 1;        // 0..127
    int lhalf = tid & 1;         // which 8-wide k chunk
    int kb    = lhalf * 8;
    const float* xsrc = x + (size_t)stok[lrow] * D_IN + kb;
    const float* wsrc = Wbase + (size_t)(o0 + lrow) * D_IN + kb;

    // preload ktile 0 into buffer 0
    float4 xr0 = *(const float4*)(xsrc);
    float4 xr1 = *(const float4*)(xsrc + 4);
    float4 wr0 = *(const float4*)(wsrc);
    float4 wr1 = *(const float4*)(wsrc + 4);
    Xs[0][kb + 0][lrow] = xr0.x; Xs[0][kb + 1][lrow] = xr0.y;
    Xs[0][kb + 2][lrow] = xr0.z; Xs[0][kb + 3][lrow] = xr0.w;
    Xs[0][kb + 4][lrow] = xr1.x; Xs[0][kb + 5][lrow] = xr1.y;
    Xs[0][kb + 6][lrow] = xr1.z; Xs[0][kb + 7][lrow] = xr1.w;
    Ws[0][kb + 0][lrow] = wr0.x; Ws[0][kb + 1][lrow] = wr0.y;
    Ws[0][kb + 2][lrow] = wr0.z; Ws[0][kb + 3][lrow] = wr0.w;
    Ws[0][kb + 4][lrow] = wr1.x; Ws[0][kb + 5][lrow] = wr1.y;
    Ws[0][kb + 6][lrow] = wr1.z; Ws[0][kb + 7][lrow] = wr1.w;
    __syncthreads();

    int tx = tid & 15, ty = tid >> 4;
    float acc[8][8];
#pragma unroll
    for (int i = 0; i < 8; i++)
#pragma unroll
        for (int j = 0; j < 8; j++) acc[i][j] = 0.f;

    int buf = 0;
    for (int k0 = 0; k0 < D_IN; k0 += BK) {
        bool has_next = (k0 + BK) < D_IN;
        if (has_next) {
            xr0 = *(const float4*)(xsrc + k0 + BK);
            xr1 = *(const float4*)(xsrc + k0 + BK + 4);
            wr0 = *(const float4*)(wsrc + k0 + BK);
            wr1 = *(const float4*)(wsrc + k0 + BK + 4);
        }
#pragma unroll
        for (int k = 0; k < BK; k++) {
            float a[8], b[8];
            *(float4*)&a[0] = *(const float4*)&Xs[buf][k][ty * 8];
            *(float4*)&a[4] = *(const float4*)&Xs[buf][k][ty * 8 + 4];
            *(float4*)&b[0] = *(const float4*)&Ws[buf][k][tx * 8];
            *(float4*)&b[4] = *(const float4*)&Ws[buf][k][tx * 8 + 4];
#pragma unroll
            for (int ii = 0; ii < 8; ii++)
#pragma unroll
                for (int jj = 0; jj < 8; jj++)
                    acc[ii][jj] = fmaf(a[ii], b[jj], acc[ii][jj]);
        }
        if (has_next) {
            int nb = buf ^ 1;
            Xs[nb][kb + 0][lrow] = xr0.x; Xs[nb][kb + 1][lrow] = xr0.y;
            Xs[nb][kb + 2][lrow] = xr0.z; Xs[nb][kb + 3][lrow] = xr0.w;
            Xs[nb][kb + 4][lrow] = xr1.x; Xs[nb][kb + 5][lrow] = xr1.y;
            Xs[nb][kb + 6][lrow] = xr1.z; Xs[nb][kb + 7][lrow] = xr1.w;
            Ws[nb][kb + 0][lrow] = wr0.x; Ws[nb][kb + 1][lrow] = wr0.y;
            Ws[nb][kb + 2][lrow] = wr0.z; Ws[nb][kb + 3][lrow] = wr0.w;
            Ws[nb][kb + 4][lrow] = wr1.x; Ws[nb][kb + 5][lrow] = wr1.y;
            Ws[nb][kb + 6][lrow] = wr1.z; Ws[nb][kb + 7][lrow] = wr1.w;
        }
        __syncthreads();
        buf ^= 1;
    }

    float bias[8];
#pragma unroll
    for (int jj = 0; jj < 8; jj++)
        bias[jj] = be[e * D_OUT + o0 + tx * 8 + jj];

#pragma unroll
    for (int ii = 0; ii < 8; ii++) {
        int row = ty * 8 + ii;
        if (row < nrows) {
            float* op = out + (size_t)stok[row] * D_OUT + o0 + tx * 8;
            float4 v0 = make_float4(acc[ii][0] + bias[0], acc[ii][1] + bias[1],
                                    acc[ii][2] + bias[2], acc[ii][3] + bias[3]);
            float4 v1 = make_float4(acc[ii][4] + bias[4], acc[ii][5] + bias[5],
                                    acc[ii][6] + bias[6], acc[ii][7] + bias[7]);
            *(float4*)op       = v0;
            *(float4*)(op + 4) = v1;
        }
    }
}

// ---------------- aux loss ----------------
__global__ void aux_kernel(float* out_aux) {
    if (threadIdx.x == 0) {
        float s = 0.f;
        for (int e = 0; e < NE; e++) {
            float mg = g_gate_sum[e] * (float)NE / (float)T_TOK;
            s += mg * mg;
        }
        *out_aux = s / (float)NE;
    }
}

// ---------------- launch ----------------
extern "C" void kernel_launch(void* const* d_in, const int* in_sizes, int n_in,
                              void* d_out, int out_size) {
    const float* x  = (const float*)d_in[0];
    const float* We = (const float*)d_in[1];
    const float* be = (const float*)d_in[2];
    const float* Wg = (const float*)d_in[3];
    const float* bg = (const float*)d_in[4];
    float* out = (float*)d_out;

    reset_kernel<<<1, 32>>>();
    gate_kernel<<<T_TOK / 8, 256>>>(x, Wg, bg);
    build_tiles_kernel<<<1, 1>>>();
    scatter_kernel<<<T_TOK / 256, 256>>>();
    dim3 grid(D_OUT / TN, MAXTILES);
    gemm_kernel<<<grid, 256>>>(x, We, be, out);
    if (out_size > T_TOK * D_OUT)
        aux_kernel<<<1, 1>>>(out + (size_t)T_TOK * D_OUT);
}

// round 3
// speedup vs baseline: 1.7808x; 1.7808x over previous
#include <cuda_runtime.h>
#include <cuda_bf16.h>
#include <cstdint>

#define T_TOK 8192
#define D_IN  1024
#define D_OUT 1024
#define NE    8
#define TM    128
#define TN    128
#define BK    32
#define KSTAGES (D_IN / BK)          // 32
#define NST   3
#define ROWB  80                     // 32 bf16 = 64B + 16B pad (conflict-free)
#define TILEB (128 * ROWB)           // 10240
#define STGB  (4 * TILEB)            // 40960: Ah|Al|Bh|Bl
#define SMEM_GEMM (NST * STGB + 1024)
#define MAXTILES (T_TOK/TM + NE)     // 72

// ---------------- device scratch ----------------
__device__ float g_gate_sum[NE];
__device__ int   g_top1[T_TOK];
__device__ int   g_count[NE];
__device__ int   g_cursor[NE];
__device__ int   g_perm[T_TOK];
__device__ int   g_tile_e[MAXTILES];
__device__ int   g_tile_row[MAXTILES];
__device__ int   g_tile_nrows[MAXTILES];
__device__ int   g_ntiles;

__device__ __nv_bfloat16 g_xh[(T_TOK + TM) * D_IN];
__device__ __nv_bfloat16 g_xl[(T_TOK + TM) * D_IN];
__device__ __nv_bfloat16 g_Weh[NE * D_OUT * D_IN];
__device__ __nv_bfloat16 g_Wel[NE * D_OUT * D_IN];

// ---------------- helpers ----------------
__device__ __forceinline__ uint32_t smem_u32(const void* p) {
    return (uint32_t)__cvta_generic_to_shared(p);
}
__device__ __forceinline__ void cpa16(uint32_t dst, const void* src) {
    asm volatile("cp.async.cg.shared.global [%0], [%1], 16;\n" :: "r"(dst), "l"(src));
}
#define CP_COMMIT() asm volatile("cp.async.commit_group;" ::: "memory")
#define CP_WAIT(n)  asm volatile("cp.async.wait_group %0;" :: "n"(n) : "memory")

__device__ __forceinline__ void ldsm4(uint32_t* r, uint32_t a) {
    asm volatile("ldmatrix.sync.aligned.m8n8.x4.shared.b16 {%0,%1,%2,%3}, [%4];"
                 : "=r"(r[0]), "=r"(r[1]), "=r"(r[2]), "=r"(r[3]) : "r"(a));
}
__device__ __forceinline__ void mma16816(float* c, const uint32_t* a, const uint32_t* b) {
    asm volatile("mma.sync.aligned.m16n8k16.row.col.f32.bf16.bf16.f32 "
                 "{%0,%1,%2,%3}, {%4,%5,%6,%7}, {%8,%9}, {%0,%1,%2,%3};"
                 : "+f"(c[0]), "+f"(c[1]), "+f"(c[2]), "+f"(c[3])
                 : "r"(a[0]), "r"(a[1]), "r"(a[2]), "r"(a[3]),
                   "r"(b[0]), "r"(b[1]));
}

// ---------------- reset ----------------
__global__ void reset_kernel() {
    int i = threadIdx.x;
    if (i < NE) { g_gate_sum[i] = 0.f; g_count[i] = 0; }
}

// ---------------- gate ----------------
__global__ void gate_kernel(const float* __restrict__ x,
                            const float* __restrict__ Wg,
                            const float* __restrict__ bg) {
    __shared__ float sWg[NE * D_IN];
    __shared__ float sSum[NE];
    int tid = threadIdx.x;
    for (int i = tid; i < NE * D_IN; i += blockDim.x) sWg[i] = Wg[i];
    if (tid < NE) sSum[tid] = 0.f;
    __syncthreads();

    int lane = tid & 31, warp = tid >> 5;
    int t = blockIdx.x * (blockDim.x >> 5) + warp;

    float acc[NE];
#pragma unroll
    for (int e = 0; e < NE; e++) acc[e] = 0.f;
    const float* xp = x + (size_t)t * D_IN;
    for (int d = lane; d < D_IN; d += 32) {
        float xv = xp[d];
#pragma unroll
        for (int e = 0; e < NE; e++) acc[e] = fmaf(xv, sWg[e * D_IN + d], acc[e]);
    }
#pragma unroll
    for (int e = 0; e < NE; e++) {
#pragma unroll
        for (int o = 16; o; o >>= 1) acc[e] += __shfl_xor_sync(0xffffffffu, acc[e], o);
    }
    if (lane == 0) {
        float m = -1e30f; int am = 0;
#pragma unroll
        for (int e = 0; e < NE; e++) {
            acc[e] += bg[e];
            if (acc[e] > m) { m = acc[e]; am = e; }
        }
        float s = 0.f, p[NE];
#pragma unroll
        for (int e = 0; e < NE; e++) { p[e] = expf(acc[e] - m); s += p[e]; }
        float inv = 1.f / s;
        g_top1[t] = am;
        atomicAdd(&g_count[am], 1);
#pragma unroll
        for (int e = 0; e < NE; e++) atomicAdd(&sSum[e], p[e] * inv);
    }
    __syncthreads();
    if (tid < NE) atomicAdd(&g_gate_sum[tid], sSum[tid]);
}

// ---------------- tile table ----------------
__global__ void build_tiles_kernel() {
    if (threadIdx.x == 0) {
        int off = 0, n = 0;
        for (int e = 0; e < NE; e++) {
            g_cursor[e] = off;
            int c = g_count[e];
            int nt = (c + TM - 1) / TM;
            for (int j = 0; j < nt; j++) {
                g_tile_e[n] = e;
                g_tile_row[n] = off + j * TM;
                int rem = c - j * TM;
                g_tile_nrows[n] = rem < TM ? rem : TM;
                n++;
            }
            off += c;
        }
        g_ntiles = n;
    }
}

// ---------------- scatter ----------------
__global__ void scatter_kernel() {
    int t = blockIdx.x * blockDim.x + threadIdx.x;
    if (t < T_TOK) {
        int e = g_top1[t];
        int p = atomicAdd(&g_cursor[e], 1);
        g_perm[p] = t;
    }
}

// ---------------- convert We -> bf16 hi/lo ----------------
__global__ void convert_We_kernel(const float* __restrict__ We) {
    size_t stride = (size_t)gridDim.x * blockDim.x * 4;
    size_t total = (size_t)NE * D_OUT * D_IN;
    for (size_t i = (size_t)(blockIdx.x * blockDim.x + threadIdx.x) * 4; i < total; i += stride) {
        float4 v = *(const float4*)(We + i);
        __nv_bfloat16 h0 = __float2bfloat16(v.x), h1 = __float2bfloat16(v.y);
        __nv_bfloat16 h2 = __float2bfloat16(v.z), h3 = __float2bfloat16(v.w);
        __nv_bfloat16 l0 = __float2bfloat16(v.x - __bfloat162float(h0));
        __nv_bfloat16 l1 = __float2bfloat16(v.y - __bfloat162float(h1));
        __nv_bfloat16 l2 = __float2bfloat16(v.z - __bfloat162float(h2));
        __nv_bfloat16 l3 = __float2bfloat16(v.w - __bfloat162float(h3));
        *(__nv_bfloat162*)(g_Weh + i)     = __nv_bfloat162(h0, h1);
        *(__nv_bfloat162*)(g_Weh + i + 2) = __nv_bfloat162(h2, h3);
        *(__nv_bfloat162*)(g_Wel + i)     = __nv_bfloat162(l0, l1);
        *(__nv_bfloat162*)(g_Wel + i + 2) = __nv_bfloat162(l2, l3);
    }
}

// ---------------- gather+convert x (permuted) ----------------
__global__ void convert_x_kernel(const float* __restrict__ x) {
    int p = blockIdx.x;
    int t = g_perm[p];
    int d = threadIdx.x * 4;
    float4 v = *(const float4*)(x + (size_t)t * D_IN + d);
    __nv_bfloat16 h0 = __float2bfloat16(v.x), h1 = __float2bfloat16(v.y);
    __nv_bfloat16 h2 = __float2bfloat16(v.z), h3 = __float2bfloat16(v.w);
    __nv_bfloat16 l0 = __float2bfloat16(v.x - __bfloat162float(h0));
    __nv_bfloat16 l1 = __float2bfloat16(v.y - __bfloat162float(h1));
    __nv_bfloat16 l2 = __float2bfloat16(v.z - __bfloat162float(h2));
    __nv_bfloat16 l3 = __float2bfloat16(v.w - __bfloat162float(h3));
    size_t o = (size_t)p * D_IN + d;
    *(__nv_bfloat162*)(g_xh + o)     = __nv_bfloat162(h0, h1);
    *(__nv_bfloat162*)(g_xh + o + 2) = __nv_bfloat162(h2, h3);
    *(__nv_bfloat162*)(g_xl + o)     = __nv_bfloat162(l0, l1);
    *(__nv_bfloat162*)(g_xl + o + 2) = __nv_bfloat162(l2, l3);
}

// ---------------- expert GEMM: mma.sync bf16 3-pass, 3-stage cp.async ----
__global__ void __launch_bounds__(256, 1)
mma_gemm_kernel(const float* __restrict__ be, float* __restrict__ out) {
    int tile = blockIdx.y;
    if (tile >= g_ntiles) return;
    int e     = g_tile_e[tile];
    int row0  = g_tile_row[tile];
    int nrows = g_tile_nrows[tile];
    int o0    = blockIdx.x * TN;

    extern __shared__ char smem[];
    uint32_t sb = smem_u32(smem);
    int tid = threadIdx.x, l = tid & 31, wid = tid >> 5;
    int wm = wid & 3, wn = wid >> 2;

    int*   stok = (int*)(smem + NST * STGB);
    float* bias = (float*)(smem + NST * STGB + 512);
    if (tid < TM) {
        int r = tid < nrows ? tid : nrows - 1;
        stok[tid] = g_perm[row0 + r];
        bias[tid] = be[e * D_OUT + o0 + tid];
    }

    const __nv_bfloat16* srcs[4];
    srcs[0] = g_xh + (size_t)row0 * D_IN;
    srcs[1] = g_xl + (size_t)row0 * D_IN;
    srcs[2] = g_Weh + ((size_t)e * D_OUT + o0) * D_IN;
    srcs[3] = g_Wel + ((size_t)e * D_OUT + o0) * D_IN;

    // precompute per-thread loader geometry: 8 chunks of 16B per stage
    const __nv_bfloat16* sp[8];
    uint32_t doff[8];
#pragma unroll
    for (int j = 0; j < 8; j++) {
        int c = tid + j * 256;
        int t4 = c >> 9;             // which tile (Ah/Al/Bh/Bl)
        int row = (c >> 2) & 127;
        int kc = c & 3;
        sp[j] = srcs[t4] + (size_t)row * D_IN + kc * 8;
        doff[j] = (uint32_t)(t4 * TILEB + row * ROWB + kc * 16);
    }

    auto load_stage = [&](int buf, int k0) {
        uint32_t base = sb + buf * STGB;
#pragma unroll
        for (int j = 0; j < 8; j++) cpa16(base + doff[j], sp[j] + k0);
    };

    // ldmatrix lane offsets (A pattern & B pattern), relative to tile base
    uint32_t aOff = (uint32_t)((wm * 32 + (l & 15)) * ROWB + ((l >> 4) & 1) * 16);
    uint32_t bOff = (uint32_t)((wn * 64 + (l & 7) + ((l >> 4) & 1) * 8) * ROWB +
                               ((l >> 3) & 1) * 16);

    load_stage(0, 0);  CP_COMMIT();
    load_stage(1, BK); CP_COMMIT();

    float acc[2][8][4];
#pragma unroll
    for (int mi = 0; mi < 2; mi++)
#pragma unroll
        for (int nj = 0; nj < 8; nj++)
#pragma unroll
            for (int q = 0; q < 4; q++) acc[mi][nj][q] = 0.f;

    __syncthreads();   // covers stok/bias too

    for (int s = 0; s < KSTAGES; s++) {
        if (s + 2 < KSTAGES) {
            int nb = s + 2; nb -= (nb >= NST) ? ((nb / NST) * NST) : 0;
            load_stage((s + 2) % NST, (s + 2) * BK);
        }
        CP_COMMIT();
        CP_WAIT(2);
        __syncthreads();

        uint32_t stb = sb + (s % NST) * STGB;
#pragma unroll
        for (int pass = 0; pass < 3; pass++) {
            uint32_t aBase = stb + aOff + (pass == 2 ? TILEB : 0);
            uint32_t bBase = stb + bOff + 2 * TILEB + (pass == 1 ? TILEB : 0);
#pragma unroll
            for (int ks = 0; ks < 2; ks++) {
                uint32_t a[2][4], b[4][4];
                ldsm4(a[0], aBase + ks * 32);
                ldsm4(a[1], aBase + ks * 32 + 16 * ROWB);
#pragma unroll
                for (int np = 0; np < 4; np++)
                    ldsm4(b[np], bBase + ks * 32 + np * 16 * ROWB);
#pragma unroll
                for (int mi = 0; mi < 2; mi++)
#pragma unroll
                    for (int nj = 0; nj < 8; nj++)
                        mma16816(acc[mi][nj], a[mi], &b[nj >> 1][(nj & 1) * 2]);
            }
        }
        __syncthreads();
    }

    // epilogue: direct global stores with bias
    int g = l >> 2, t2 = (l & 3) * 2;
#pragma unroll
    for (int mi = 0; mi < 2; mi++) {
#pragma unroll
        for (int half = 0; half < 2; half++) {
            int row = wm * 32 + mi * 16 + g + half * 8;
            if (row < nrows) {
                float* op = out + (size_t)stok[row] * D_OUT + o0;
#pragma unroll
                for (int nj = 0; nj < 8; nj++) {
                    int col = wn * 64 + nj * 8 + t2;
                    float2 v;
                    v.x = acc[mi][nj][half * 2 + 0] + bias[col];
                    v.y = acc[mi][nj][half * 2 + 1] + bias[col + 1];
                    *(float2*)(op + col) = v;
                }
            }
        }
    }
}

// ---------------- aux loss ----------------
__global__ void aux_kernel(float* out_aux) {
    if (threadIdx.x == 0) {
        float s = 0.f;
        for (int e = 0; e < NE; e++) {
            float mg = g_gate_sum[e] * (float)NE / (float)T_TOK;
            s += mg * mg;
        }
        *out_aux = s / (float)NE;
    }
}

// ---------------- launch ----------------
extern "C" void kernel_launch(void* const* d_in, const int* in_sizes, int n_in,
                              void* d_out, int out_size) {
    const float* x  = (const float*)d_in[0];
    const float* We = (const float*)d_in[1];
    const float* be = (const float*)d_in[2];
    const float* Wg = (const float*)d_in[3];
    const float* bg = (const float*)d_in[4];
    float* out = (float*)d_out;

    cudaFuncSetAttribute(mma_gemm_kernel,
                         cudaFuncAttributeMaxDynamicSharedMemorySize, SMEM_GEMM);

    reset_kernel<<<1, 32>>>();
    gate_kernel<<<T_TOK / 8, 256>>>(x, Wg, bg);
    convert_We_kernel<<<4096, 256>>>(We);
    build_tiles_kernel<<<1, 1>>>();
    scatter_kernel<<<T_TOK / 256, 256>>>();
    convert_x_kernel<<<T_TOK, 256>>>(x);
    dim3 grid(D_OUT / TN, MAXTILES);
    mma_gemm_kernel<<<grid, 256, SMEM_GEMM>>>(be, out);
    if (out_size > T_TOK * D_OUT)
        aux_kernel<<<1, 1>>>(out + (size_t)T_TOK * D_OUT);
}

// round 4
// speedup vs baseline: 1.8563x; 1.0424x over previous
#include <cuda_runtime.h>
#include <cuda_bf16.h>
#include <cstdint>

#define T_TOK 8192
#define D_IN  1024
#define D_OUT 1024
#define NE    8
#define TM    128
#define TN    128
#define BK    32
#define KSTAGES (D_IN / BK)          // 32
#define NST   3
#define ROWB  80                     // 32 bf16 = 64B + 16B pad (conflict-free)
#define TILEB (128 * ROWB)           // 10240
#define STGB  (4 * TILEB)            // 40960: Ah|Al|Bh|Bl
#define SMEM_GEMM (NST * STGB + 1024)
#define MAXTILES (T_TOK/TM + NE)     // 72
#define GATE_BLKS (T_TOK / 8)        // 1024

// ---------------- device scratch ----------------
__device__ float g_gate_part[GATE_BLKS * NE];
__device__ int   g_top1[T_TOK];
__device__ int   g_cursor[NE];
__device__ int   g_perm[T_TOK];
__device__ int   g_tile_e[MAXTILES];
__device__ int   g_tile_row[MAXTILES];
__device__ int   g_tile_nrows[MAXTILES];
__device__ int   g_ntiles;

__device__ __nv_bfloat16 g_xh[(T_TOK + TM) * D_IN];
__device__ __nv_bfloat16 g_xl[(T_TOK + TM) * D_IN];
__device__ __nv_bfloat16 g_Weh[NE * D_OUT * D_IN];
__device__ __nv_bfloat16 g_Wel[NE * D_OUT * D_IN];

// ---------------- helpers ----------------
__device__ __forceinline__ uint32_t smem_u32(const void* p) {
    return (uint32_t)__cvta_generic_to_shared(p);
}
__device__ __forceinline__ void cpa16(uint32_t dst, const void* src) {
    asm volatile("cp.async.cg.shared.global [%0], [%1], 16;\n" :: "r"(dst), "l"(src));
}
#define CP_COMMIT() asm volatile("cp.async.commit_group;" ::: "memory")
#define CP_WAIT(n)  asm volatile("cp.async.wait_group %0;" :: "n"(n) : "memory")

__device__ __forceinline__ void ldsm4(uint32_t* r, uint32_t a) {
    asm volatile("ldmatrix.sync.aligned.m8n8.x4.shared.b16 {%0,%1,%2,%3}, [%4];"
                 : "=r"(r[0]), "=r"(r[1]), "=r"(r[2]), "=r"(r[3]) : "r"(a));
}
__device__ __forceinline__ void mma16816(float* c, const uint32_t* a, const uint32_t* b) {
    asm volatile("mma.sync.aligned.m16n8k16.row.col.f32.bf16.bf16.f32 "
                 "{%0,%1,%2,%3}, {%4,%5,%6,%7}, {%8,%9}, {%0,%1,%2,%3};"
                 : "+f"(c[0]), "+f"(c[1]), "+f"(c[2]), "+f"(c[3])
                 : "r"(a[0]), "r"(a[1]), "r"(a[2]), "r"(a[3]),
                   "r"(b[0]), "r"(b[1]));
}

// ---------------- gate: logits, softmax, top1; NO global atomics --------
__global__ void gate_kernel(const float* __restrict__ x,
                            const float* __restrict__ Wg,
                            const float* __restrict__ bg) {
    __shared__ float sWg[NE * D_IN];
    __shared__ float sSum[NE];
    int tid = threadIdx.x;
    for (int i = tid; i < NE * D_IN; i += blockDim.x) sWg[i] = Wg[i];
    if (tid < NE) sSum[tid] = 0.f;
    __syncthreads();

    int lane = tid & 31, warp = tid >> 5;
    int t = blockIdx.x * 8 + warp;

    float acc[NE];
#pragma unroll
    for (int e = 0; e < NE; e++) acc[e] = 0.f;
    const float* xp = x + (size_t)t * D_IN;
    for (int d = lane; d < D_IN; d += 32) {
        float xv = xp[d];
#pragma unroll
        for (int e = 0; e < NE; e++) acc[e] = fmaf(xv, sWg[e * D_IN + d], acc[e]);
    }
#pragma unroll
    for (int e = 0; e < NE; e++) {
#pragma unroll
        for (int o = 16; o; o >>= 1) acc[e] += __shfl_xor_sync(0xffffffffu, acc[e], o);
    }
    if (lane == 0) {
        float m = -1e30f; int am = 0;
#pragma unroll
        for (int e = 0; e < NE; e++) {
            acc[e] += bg[e];
            if (acc[e] > m) { m = acc[e]; am = e; }
        }
        float s = 0.f, p[NE];
#pragma unroll
        for (int e = 0; e < NE; e++) { p[e] = expf(acc[e] - m); s += p[e]; }
        float inv = 1.f / s;
        g_top1[t] = am;
#pragma unroll
        for (int e = 0; e < NE; e++) atomicAdd(&sSum[e], p[e] * inv);
    }
    __syncthreads();
    if (tid < NE) g_gate_part[blockIdx.x * NE + tid] = sSum[tid];
}

// ---------------- mid: histogram + tile table + cursors + aux ------------
__global__ void mid_kernel(float* __restrict__ out_aux, int has_aux) {
    __shared__ int   hcnt[NE];
    __shared__ float ssum[NE];
    int tid = threadIdx.x;
    if (tid < NE) { hcnt[tid] = 0; ssum[tid] = 0.f; }
    __syncthreads();

    // histogram: local counts then smem atomics
    int lc[NE];
#pragma unroll
    for (int e = 0; e < NE; e++) lc[e] = 0;
    for (int t = tid; t < T_TOK; t += 256) lc[g_top1[t]]++;
#pragma unroll
    for (int e = 0; e < NE; e++) if (lc[e]) atomicAdd(&hcnt[e], lc[e]);

    // gate prob sums for aux
    float ls[NE];
#pragma unroll
    for (int e = 0; e < NE; e++) ls[e] = 0.f;
    for (int j = tid; j < GATE_BLKS; j += 256) {
#pragma unroll
        for (int e = 0; e < NE; e++) ls[e] += g_gate_part[j * NE + e];
    }
#pragma unroll
    for (int e = 0; e < NE; e++) {
#pragma unroll
        for (int o = 16; o; o >>= 1) ls[e] += __shfl_xor_sync(0xffffffffu, ls[e], o);
        if ((tid & 31) == 0) atomicAdd(&ssum[e], ls[e]);
    }
    __syncthreads();

    if (tid == 0) {
        int off = 0, n = 0;
        for (int e = 0; e < NE; e++) {
            g_cursor[e] = off;
            int c = hcnt[e];
            int nt = (c + TM - 1) / TM;
            for (int j = 0; j < nt; j++) {
                g_tile_e[n] = e;
                g_tile_row[n] = off + j * TM;
                int rem = c - j * TM;
                g_tile_nrows[n] = rem < TM ? rem : TM;
                n++;
            }
            off += c;
        }
        g_ntiles = n;
        if (has_aux) {
            float s = 0.f;
            for (int e = 0; e < NE; e++) {
                float mg = ssum[e] * (float)NE / (float)T_TOK;
                s += mg * mg;
            }
            *out_aux = s / (float)NE;
        }
    }
}

// ---------------- fused scatter + gather-convert x ------------------------
__global__ void scatter_convert_kernel(const float* __restrict__ x) {
    int lane = threadIdx.x & 31, warp = threadIdx.x >> 5;
    int t = blockIdx.x * 8 + warp;
    int p;
    if (lane == 0) {
        int e = g_top1[t];
        p = atomicAdd(&g_cursor[e], 1);
        g_perm[p] = t;
    }
    p = __shfl_sync(0xffffffffu, p, 0);

    const float* xp = x + (size_t)t * D_IN;
    __nv_bfloat16* oh = g_xh + (size_t)p * D_IN;
    __nv_bfloat16* ol = g_xl + (size_t)p * D_IN;
#pragma unroll
    for (int i = 0; i < 8; i++) {
        int d = lane * 4 + i * 128;
        float4 v = *(const float4*)(xp + d);
        __nv_bfloat16 h0 = __float2bfloat16(v.x), h1 = __float2bfloat16(v.y);
        __nv_bfloat16 h2 = __float2bfloat16(v.z), h3 = __float2bfloat16(v.w);
        __nv_bfloat16 l0 = __float2bfloat16(v.x - __bfloat162float(h0));
        __nv_bfloat16 l1 = __float2bfloat16(v.y - __bfloat162float(h1));
        __nv_bfloat16 l2 = __float2bfloat16(v.z - __bfloat162float(h2));
        __nv_bfloat16 l3 = __float2bfloat16(v.w - __bfloat162float(h3));
        *(__nv_bfloat162*)(oh + d)     = __nv_bfloat162(h0, h1);
        *(__nv_bfloat162*)(oh + d + 2) = __nv_bfloat162(h2, h3);
        *(__nv_bfloat162*)(ol + d)     = __nv_bfloat162(l0, l1);
        *(__nv_bfloat162*)(ol + d + 2) = __nv_bfloat162(l2, l3);
    }
}

// ---------------- convert We -> bf16 hi/lo ----------------
__global__ void convert_We_kernel(const float* __restrict__ We) {
    size_t stride = (size_t)gridDim.x * blockDim.x * 4;
    size_t total = (size_t)NE * D_OUT * D_IN;
    for (size_t i = (size_t)(blockIdx.x * blockDim.x + threadIdx.x) * 4; i < total; i += stride) {
        float4 v = *(const float4*)(We + i);
        __nv_bfloat16 h0 = __float2bfloat16(v.x), h1 = __float2bfloat16(v.y);
        __nv_bfloat16 h2 = __float2bfloat16(v.z), h3 = __float2bfloat16(v.w);
        __nv_bfloat16 l0 = __float2bfloat16(v.x - __bfloat162float(h0));
        __nv_bfloat16 l1 = __float2bfloat16(v.y - __bfloat162float(h1));
        __nv_bfloat16 l2 = __float2bfloat16(v.z - __bfloat162float(h2));
        __nv_bfloat16 l3 = __float2bfloat16(v.w - __bfloat162float(h3));
        *(__nv_bfloat162*)(g_Weh + i)     = __nv_bfloat162(h0, h1);
        *(__nv_bfloat162*)(g_Weh + i + 2) = __nv_bfloat162(h2, h3);
        *(__nv_bfloat162*)(g_Wel + i)     = __nv_bfloat162(l0, l1);
        *(__nv_bfloat162*)(g_Wel + i + 2) = __nv_bfloat162(l2, l3);
    }
}

// ---------------- expert GEMM: bf16 3-pass, frag-once, 1 sync/stage ------
__global__ void __launch_bounds__(256, 1)
mma_gemm_kernel(const float* __restrict__ be, float* __restrict__ out) {
    int tile = blockIdx.y;
    if (tile >= g_ntiles) return;
    int e     = g_tile_e[tile];
    int row0  = g_tile_row[tile];
    int nrows = g_tile_nrows[tile];
    int o0    = blockIdx.x * TN;

    extern __shared__ char smem[];
    uint32_t sb = smem_u32(smem);
    int tid = threadIdx.x, l = tid & 31, wid = tid >> 5;
    int wm = wid & 3, wn = wid >> 2;

    int*   stok = (int*)(smem + NST * STGB);
    float* bias = (float*)(smem + NST * STGB + 512);
    if (tid < TM) {
        int r = tid < nrows ? tid : nrows - 1;
        stok[tid] = g_perm[row0 + r];
        bias[tid] = be[e * D_OUT + o0 + tid];
    }

    const __nv_bfloat16* srcs[4];
    srcs[0] = g_xh + (size_t)row0 * D_IN;
    srcs[1] = g_xl + (size_t)row0 * D_IN;
    srcs[2] = g_Weh + ((size_t)e * D_OUT + o0) * D_IN;
    srcs[3] = g_Wel + ((size_t)e * D_OUT + o0) * D_IN;

    const __nv_bfloat16* sp[8];
    uint32_t doff[8];
#pragma unroll
    for (int j = 0; j < 8; j++) {
        int c = tid + j * 256;
        int t4 = c >> 9;
        int row = (c >> 2) & 127;
        int kc = c & 3;
        sp[j] = srcs[t4] + (size_t)row * D_IN + kc * 8;
        doff[j] = (uint32_t)(t4 * TILEB + row * ROWB + kc * 16);
    }

    auto load_stage = [&](int buf, int k0) {
        uint32_t base = sb + buf * STGB;
#pragma unroll
        for (int j = 0; j < 8; j++) cpa16(base + doff[j], sp[j] + k0);
    };

    uint32_t aOff = (uint32_t)((wm * 32 + (l & 15)) * ROWB + ((l >> 4) & 1) * 16);
    uint32_t bOff = (uint32_t)(2 * TILEB + (wn * 64 + (l & 7) + ((l >> 4) & 1) * 8) * ROWB +
                               ((l >> 3) & 1) * 16);

    load_stage(0, 0);  CP_COMMIT();
    load_stage(1, BK); CP_COMMIT();

    float acc[2][8][4];
#pragma unroll
    for (int mi = 0; mi < 2; mi++)
#pragma unroll
        for (int nj = 0; nj < 8; nj++)
#pragma unroll
            for (int q = 0; q < 4; q++) acc[mi][nj][q] = 0.f;

    __syncthreads();   // stok/bias ready; also pre-mainloop barrier

    for (int s = 0; s < KSTAGES; s++) {
        CP_WAIT(1);
        __syncthreads();
        if (s + 2 < KSTAGES) load_stage((s + 2) % NST, (s + 2) * BK);
        CP_COMMIT();

        uint32_t stb = sb + (s % NST) * STGB;
#pragma unroll
        for (int ks = 0; ks < 2; ks++) {
            uint32_t ah[2][4], al[2][4], bh[4][4], bl[4][4];
            uint32_t aB = stb + aOff + ks * 32;
            uint32_t bB = stb + bOff + ks * 32;
            ldsm4(ah[0], aB);
            ldsm4(ah[1], aB + 16 * ROWB);
            ldsm4(al[0], aB + TILEB);
            ldsm4(al[1], aB + TILEB + 16 * ROWB);
#pragma unroll
            for (int np = 0; np < 4; np++) {
                ldsm4(bh[np], bB + np * 16 * ROWB);
                ldsm4(bl[np], bB + TILEB + np * 16 * ROWB);
            }
#pragma unroll
            for (int mi = 0; mi < 2; mi++)
#pragma unroll
                for (int nj = 0; nj < 8; nj++) {
                    mma16816(acc[mi][nj], ah[mi], &bh[nj >> 1][(nj & 1) * 2]);
                    mma16816(acc[mi][nj], ah[mi], &bl[nj >> 1][(nj & 1) * 2]);
                    mma16816(acc[mi][nj], al[mi], &bh[nj >> 1][(nj & 1) * 2]);
                }
        }
    }

    // epilogue
    int g = l >> 2, t2 = (l & 3) * 2;
#pragma unroll
    for (int mi = 0; mi < 2; mi++) {
#pragma unroll
        for (int half = 0; half < 2; half++) {
            int row = wm * 32 + mi * 16 + g + half * 8;
            if (row < nrows) {
                float* op = out + (size_t)stok[row] * D_OUT + o0;
#pragma unroll
                for (int nj = 0; nj < 8; nj++) {
                    int col = wn * 64 + nj * 8 + t2;
                    float2 v;
                    v.x = acc[mi][nj][half * 2 + 0] + bias[col];
                    v.y = acc[mi][nj][half * 2 + 1] + bias[col + 1];
                    *(float2*)(op + col) = v;
                }
            }
        }
    }
}

// ---------------- launch ----------------
extern "C" void kernel_launch(void* const* d_in, const int* in_sizes, int n_in,
                              void* d_out, int out_size) {
    const float* x  = (const float*)d_in[0];
    const float* We = (const float*)d_in[1];
    const float* be = (const float*)d_in[2];
    const float* Wg = (const float*)d_in[3];
    const float* bg = (const float*)d_in[4];
    float* out = (float*)d_out;

    cudaFuncSetAttribute(mma_gemm_kernel,
                         cudaFuncAttributeMaxDynamicSharedMemorySize, SMEM_GEMM);

    int has_aux = out_size > T_TOK * D_OUT;
    convert_We_kernel<<<4096, 256>>>(We);
    gate_kernel<<<GATE_BLKS, 256>>>(x, Wg, bg);
    mid_kernel<<<1, 256>>>(out + (size_t)T_TOK * D_OUT, has_aux);
    scatter_convert_kernel<<<T_TOK / 8, 256>>>(x);
    dim3 grid(D_OUT / TN, MAXTILES);
    mma_gemm_kernel<<<grid, 256, SMEM_GEMM>>>(be, out);
}